// round 1
// baseline (speedup 1.0000x reference)
#include <cuda_runtime.h>
#include <cuda_bf16.h>
#include <cstdint>

// LocalPatternExtractor: the reference forward pass is identically zero.
//
// Proof: quantize_pot_ste clamps the membrane potential to
//   q = clip(round(v * 128), -128, 127) / 128  =>  q_max = 127/128 = 0.9921875.
// The spike's forward value is the hard threshold (mem >= THRESHOLD=1.0)
// (the sigmoid surrogate cancels: surr + (hard - surr) = hard), which is
// therefore 0 for every element at every timestep. acc stays 0, so
//   out = acc / TIMESTEPS = 0  (shape 16x256x5000), reg_loss = 0.01*mean(0) = 0.
// Every element of d_out is exactly 0.0f. The conv/GEMM/BN stages are dead
// code in the forward value. The optimal kernel is a pure zero-fill,
// bounded by HBM store bandwidth (~82 MB of writes).

__global__ void zero_fill_vec4(float4* __restrict__ out4, size_t n4,
                               float* __restrict__ tail, int ntail) {
    size_t i = (size_t)blockIdx.x * blockDim.x + threadIdx.x;
    const float4 z = make_float4(0.f, 0.f, 0.f, 0.f);
    if (i < n4) out4[i] = z;
    // first few threads of block 0 handle the non-multiple-of-4 tail
    if (blockIdx.x == 0 && (int)threadIdx.x < ntail) tail[threadIdx.x] = 0.f;
}

extern "C" void kernel_launch(void* const* d_in, const int* in_sizes, int n_in,
                              void* d_out, int out_size) {
    (void)d_in; (void)in_sizes; (void)n_in;
    float* out = (float*)d_out;
    size_t n = (size_t)out_size;          // 20,480,001 expected (out + reg_loss)
    size_t n4 = n >> 2;                   // float4 stores
    int ntail = (int)(n & 3);
    float* tail = out + (n4 << 2);

    const int threads = 256;
    size_t blocks = (n4 + threads - 1) / threads;
    if (blocks == 0) blocks = 1;
    zero_fill_vec4<<<(unsigned)blocks, threads>>>(
        (float4*)out, n4, tail, ntail);
}